// round 2
// baseline (speedup 1.0000x reference)
#include <cuda_runtime.h>
#include <math.h>

#define NN 207
#define BB 32
#define TT 12
#define CC 2
#define HORZ 12
#define DID 64
#define HH 128
#define CONCATN 2560          // DID + TT + NN*TT
#define MROWS (BB*NN*CC)      // 13248
#define MPAD 13312            // 104 * 128
#define BNCNT (BB*NN)         // 6624
#define EPSILON_V 10.0f
#define EPS_V 1e-8f

// ---------------- scratch (device globals; no allocation) ----------------
__device__ float g_X[(size_t)MPAD * CONCATN];    // (b,n,c, CONCAT) ~136MB (M-padded)
__device__ float g_H0[MPAD * HH];
__device__ float g_H1[MPAD * HH];
__device__ float g_F[MPAD * HORZ];               // (b,n,c, HOR)
__device__ float g_hin[BNCNT * TT * CC];         // h_in
__device__ float g_level[BNCNT * CC];
__device__ float g_tgf[BNCNT * HORZ];
__device__ float g_dp[NN * NN];

// ---------------- time gates + h_in + level ----------------
__global__ void timegate_kernel(const float* __restrict__ hist,
                                const float* __restrict__ tod,
                                const float* __restrict__ emb,
                                const float* __restrict__ w1, const float* __restrict__ b1,
                                const float* __restrict__ w2, const float* __restrict__ b2,
                                const float* __restrict__ w3, const float* __restrict__ b3) {
    int bn = blockIdx.x;
    int n = bn % NN;
    __shared__ float sin_[DID + TT];
    __shared__ float stg[HH];
    __shared__ float stgb[TT];
    __shared__ float shin[TT * CC];
    int t = threadIdx.x;  // 128
    if (t < DID) sin_[t] = emb[n * DID + t];
    else if (t < DID + TT) sin_[t] = tod[bn * TT + (t - DID)];
    __syncthreads();
    float acc = b1[t];
#pragma unroll 4
    for (int i = 0; i < DID + TT; i++) acc += sin_[i] * w1[i * HH + t];
    stg[t] = fmaxf(acc, 0.f);
    __syncthreads();
    if (t < HORZ) {
        float a2 = b2[t], a3 = b3[t];
#pragma unroll 8
        for (int h = 0; h < HH; h++) {
            float v = stg[h];
            a2 += v * w2[h * HORZ + t];
            a3 += v * w3[h * TT + t];
        }
        g_tgf[bn * HORZ + t] = a2;
        stgb[t] = a3;
    }
    __syncthreads();
    if (t < TT * CC) {
        int tt = t >> 1, c = t & 1;
        float hv = hist[((size_t)bn * TT + tt) * CC + c] / (1.f + stgb[tt]);
        shin[t] = hv;
        g_hin[bn * TT * CC + t] = hv;
    }
    __syncthreads();
    if (t < CC) {
        float mx = -1e30f;
#pragma unroll
        for (int tt = 0; tt < TT; tt++) mx = fmaxf(mx, shin[tt * CC + t]);
        g_level[bn * CC + t] = mx;
    }
}

// ---------------- pairwise affinities ----------------
__global__ void dp_kernel(const float* __restrict__ emb) {
    int idx = blockIdx.x * blockDim.x + threadIdx.x;
    if (idx >= NN * NN) return;
    int i = idx / NN, j = idx % NN;
    float s = 0.f;
#pragma unroll 8
    for (int k = 0; k < DID; k++) s += emb[i * DID + k] * emb[j * DID + k];
    g_dp[idx] = expf(EPSILON_V * s);
}

// ---------------- zero the M-pad rows of X ----------------
__global__ void pad_zero_kernel() {
    int idx = blockIdx.x * blockDim.x + threadIdx.x;
    int total = (MPAD - MROWS) * CONCATN;
    if (idx < total) g_X[(size_t)MROWS * CONCATN + idx] = 0.f;
}

// ---------------- build X = hist (b,n,c,CONCAT) ----------------
__global__ void build_hist_kernel(const float* __restrict__ emb) {
    int bn = blockIdx.x;
    int b = bn / NN, n = bn % NN;
    __shared__ float sh[NN * TT * CC];   // 4968 floats
    __shared__ float sdp[NN];
    __shared__ float slvl[CC];
    int tid = threadIdx.x;
    for (int i = tid; i < NN * TT * CC; i += blockDim.x) sh[i] = g_hin[b * NN * TT * CC + i];
    for (int i = tid; i < NN; i += blockDim.x) sdp[i] = g_dp[n * NN + i];
    if (tid < CC) slvl[tid] = g_level[bn * CC + tid];
    __syncthreads();
    float lv0 = slvl[0], lv1 = slvl[1];
    float rl0 = 1.f / (lv0 + EPS_V), rl1 = 1.f / (lv1 + EPS_V);
    for (int idx = tid; idx < CC * CONCATN; idx += blockDim.x) {
        int c = idx / CONCATN;
        int k = idx - c * CONCATN;
        float lv = c ? lv1 : lv0;
        float rl = c ? rl1 : rl0;
        float val;
        if (k < TT) {
            val = sh[(n * TT + k) * CC + c] * rl;
        } else if (k < TT + NN * TT) {
            int m = k - TT;
            float a = sh[m * CC + c] * sdp[m / TT];
            val = fmaxf((a - lv) * rl, 0.f);
        } else {
            val = emb[n * DID + (k - TT - NN * TT)];
        }
        g_X[((size_t)bn * CC + c) * CONCATN + k] = val;
    }
}

// ---------------- 128x64 tiled SGEMM, 8x8 microtile, 128 threads ----------------
// EPI: 0 = relu store, 1 = residual: Cout = relu(Cout - (acc+bias)) in-place
// Requires: M padded to multiple of 128 (scratch buffers are), Nout % 64 == 0,
// K % 16 == 0. No bounds checks.
#define GBM 128
#define GBN 64
#define GBK 16

template <int EPI>
__global__ void __launch_bounds__(128) gemm128_kernel(
        const float* __restrict__ A, const float* __restrict__ Bw,
        const float* __restrict__ bias, float* __restrict__ Cout,
        int Nout, int K) {
    __shared__ float As[GBK][GBM];   // k-major (transposed A tile)
    __shared__ float Bs[GBK][GBN];
    int m0 = blockIdx.x * GBM;
    int n0 = blockIdx.y * GBN;
    int tid = threadIdx.x;           // 128
    int tx = tid & 7;                // col group 0..7
    int ty = tid >> 3;               // row group 0..15

    const float* Arow = A + (size_t)(m0 + tid) * K;   // thread owns row tid of tile
    // B tile: 16x64 = 256 float4; thread loads float4 f0=tid*2, f1=tid*2+1
    int bf0 = tid * 2;
    int bk0 = bf0 >> 4, bn0 = (bf0 & 15) * 4;
    int bf1 = bf0 + 1;
    int bk1 = bf1 >> 4, bn1 = (bf1 & 15) * 4;

    float acc[8][8];
#pragma unroll
    for (int i = 0; i < 8; i++)
#pragma unroll
        for (int j = 0; j < 8; j++) acc[i][j] = 0.f;

    for (int k0 = 0; k0 < K; k0 += GBK) {
        // load A: 4 float4 per thread (row tid, k0..k0+15), store transposed
#pragma unroll
        for (int q = 0; q < 4; q++) {
            float4 av = *reinterpret_cast<const float4*>(Arow + k0 + q * 4);
            As[q * 4 + 0][tid] = av.x;
            As[q * 4 + 1][tid] = av.y;
            As[q * 4 + 2][tid] = av.z;
            As[q * 4 + 3][tid] = av.w;
        }
        // load B: 2 float4 per thread
        *reinterpret_cast<float4*>(&Bs[bk0][bn0]) =
            *reinterpret_cast<const float4*>(&Bw[(size_t)(k0 + bk0) * Nout + n0 + bn0]);
        *reinterpret_cast<float4*>(&Bs[bk1][bn1]) =
            *reinterpret_cast<const float4*>(&Bw[(size_t)(k0 + bk1) * Nout + n0 + bn1]);
        __syncthreads();
#pragma unroll
        for (int k = 0; k < GBK; k++) {
            float4 a0 = *reinterpret_cast<const float4*>(&As[k][ty * 8]);
            float4 a1 = *reinterpret_cast<const float4*>(&As[k][ty * 8 + 4]);
            float4 b0 = *reinterpret_cast<const float4*>(&Bs[k][tx * 8]);
            float4 b1 = *reinterpret_cast<const float4*>(&Bs[k][tx * 8 + 4]);
            float a[8] = {a0.x, a0.y, a0.z, a0.w, a1.x, a1.y, a1.z, a1.w};
            float b[8] = {b0.x, b0.y, b0.z, b0.w, b1.x, b1.y, b1.z, b1.w};
#pragma unroll
            for (int i = 0; i < 8; i++)
#pragma unroll
                for (int j = 0; j < 8; j++) acc[i][j] += a[i] * b[j];
        }
        __syncthreads();
    }

#pragma unroll
    for (int i = 0; i < 8; i++) {
        int row = m0 + ty * 8 + i;
#pragma unroll
        for (int j = 0; j < 8; j++) {
            int col = n0 + tx * 8 + j;
            float v = acc[i][j] + bias[col];
            size_t off = (size_t)row * Nout + col;
            if (EPI == 0) Cout[off] = fmaxf(v, 0.f);
            else Cout[off] = fmaxf(Cout[off] - v, 0.f);
        }
    }
}

// ---------------- small GEMM for forecast head (Nout=12) ----------------
// EPI: 2 = plain store, 3 = accumulate (+=)
#define BM 64
#define BN 64
#define BKK 16

template <int EPI>
__global__ void sgemm_kernel(const float* __restrict__ A, const float* __restrict__ Bw,
                             const float* __restrict__ bias, float* __restrict__ Cout,
                             int M, int Nout, int K) {
    __shared__ float As[BKK][BM + 4];
    __shared__ float Bs[BKK][BN];
    int m0 = blockIdx.x * BM;
    int n0 = blockIdx.y * BN;
    int tid = threadIdx.x;              // 256
    int tx = tid & 15, ty = tid >> 4;
    float acc[4][4] = {};

    int arow = tid >> 2;
    int ac4 = (tid & 3) * 4;
    int bk = tid >> 4;
    int bn4 = (tid & 15) * 4;

    for (int k0 = 0; k0 < K; k0 += BKK) {
        float4 av = *reinterpret_cast<const float4*>(&A[(size_t)(m0 + arow) * K + k0 + ac4]);
        As[ac4 + 0][arow] = av.x;
        As[ac4 + 1][arow] = av.y;
        As[ac4 + 2][arow] = av.z;
        As[ac4 + 3][arow] = av.w;
#pragma unroll
        for (int j = 0; j < 4; j++) {
            int nc = n0 + bn4 + j;
            Bs[bk][bn4 + j] = (nc < Nout) ? Bw[(size_t)(k0 + bk) * Nout + nc] : 0.f;
        }
        __syncthreads();
#pragma unroll
        for (int k = 0; k < BKK; k++) {
            float4 a4 = *reinterpret_cast<const float4*>(&As[k][ty * 4]);
            float4 b4 = *reinterpret_cast<const float4*>(&Bs[k][tx * 4]);
            float a[4] = {a4.x, a4.y, a4.z, a4.w};
            float b[4] = {b4.x, b4.y, b4.z, b4.w};
#pragma unroll
            for (int i = 0; i < 4; i++)
#pragma unroll
                for (int j = 0; j < 4; j++) acc[i][j] += a[i] * b[j];
        }
        __syncthreads();
    }

#pragma unroll
    for (int i = 0; i < 4; i++) {
        int row = m0 + ty * 4 + i;
#pragma unroll
        for (int j = 0; j < 4; j++) {
            int col = n0 + tx * 4 + j;
            if (col < Nout) {
                float v = acc[i][j] + bias[col];
                size_t off = (size_t)row * Nout + col;
                if (EPI == 2) Cout[off] = v;
                else Cout[off] += v;
            }
        }
    }
}

// ---------------- outputs ----------------
__global__ void backcast_out_kernel(float* __restrict__ out) {
    int bn = blockIdx.x;
    const float* x0 = &g_X[(size_t)bn * CC * CONCATN];
    float2* o = reinterpret_cast<float2*>(out) + (size_t)bn * CONCATN;
    for (int k = threadIdx.x; k < CONCATN; k += blockDim.x) {
        float2 v;
        v.x = x0[k];
        v.y = x0[CONCATN + k];
        o[k] = v;
    }
}

__global__ void forecast_out_kernel(float* __restrict__ out) {
    int idx = blockIdx.x * blockDim.x + threadIdx.x;
    if (idx >= BNCNT * HORZ * CC) return;
    int c = idx & 1;
    int h = (idx >> 1) % HORZ;
    int bn = idx / (HORZ * CC);
    float v = g_F[((size_t)bn * CC + c) * HORZ + h];
    v *= g_level[bn * CC + c];
    v *= (1.f + g_tgf[bn * HORZ + h]);
    out[idx] = v;
}

// ---------------- launcher ----------------
extern "C" void kernel_launch(void* const* d_in, const int* in_sizes, int n_in,
                              void* d_out, int out_size) {
    const float* history = (const float*)d_in[0];
    const float* tod     = (const float*)d_in[1];
    const float* emb     = (const float*)d_in[2];
    const float* tg1_w = (const float*)d_in[3];
    const float* tg1_b = (const float*)d_in[4];
    const float* tg2_w = (const float*)d_in[5];
    const float* tg2_b = (const float*)d_in[6];
    const float* tg3_w = (const float*)d_in[7];
    const float* tg3_b = (const float*)d_in[8];
    const float* fc0_w = (const float*)d_in[9];
    const float* fc0_b = (const float*)d_in[10];
    const float* fc_w  = (const float*)d_in[11];
    const float* fc_b  = (const float*)d_in[12];
    const float* fore_w = (const float*)d_in[13];
    const float* fore_b = (const float*)d_in[14];
    const float* back_w = (const float*)d_in[15];
    const float* back_b = (const float*)d_in[16];
    float* out = (float*)d_out;

    float *pX, *pH0, *pH1, *pF;
    cudaGetSymbolAddress((void**)&pX, g_X);
    cudaGetSymbolAddress((void**)&pH0, g_H0);
    cudaGetSymbolAddress((void**)&pH1, g_H1);
    cudaGetSymbolAddress((void**)&pF, g_F);

    timegate_kernel<<<BNCNT, 128>>>(history, tod, emb, tg1_w, tg1_b, tg2_w, tg2_b, tg3_w, tg3_b);
    dp_kernel<<<(NN * NN + 255) / 256, 256>>>(emb);
    pad_zero_kernel<<<((MPAD - MROWS) * CONCATN + 255) / 256, 256>>>();
    build_hist_kernel<<<BNCNT, 256>>>(emb);

    const int GM = MPAD / GBM;   // 104
    for (int i = 0; i < 3; i++) {
        const float* w0 = fc0_w + (size_t)i * CONCATN * HH;
        const float* b0 = fc0_b + i * HH;
        gemm128_kernel<0><<<dim3(GM, HH / GBN), 128>>>(pX, w0, b0, pH0, HH, CONCATN);
        gemm128_kernel<0><<<dim3(GM, HH / GBN), 128>>>(
            pH0, fc_w + ((size_t)i * 2 + 0) * HH * HH, fc_b + (i * 2 + 0) * HH, pH1, HH, HH);
        gemm128_kernel<0><<<dim3(GM, HH / GBN), 128>>>(
            pH1, fc_w + ((size_t)i * 2 + 1) * HH * HH, fc_b + (i * 2 + 1) * HH, pH0, HH, HH);
        if (i == 0)
            sgemm_kernel<2><<<dim3(MPAD / BM, 1), 256>>>(
                pH0, fore_w + (size_t)i * HH * HORZ, fore_b + i * HORZ, pF, MPAD, HORZ, HH);
        else
            sgemm_kernel<3><<<dim3(MPAD / BM, 1), 256>>>(
                pH0, fore_w + (size_t)i * HH * HORZ, fore_b + i * HORZ, pF, MPAD, HORZ, HH);
        gemm128_kernel<1><<<dim3(GM, CONCATN / GBN), 128>>>(
            pH0, back_w + (size_t)i * HH * CONCATN, back_b + (size_t)i * CONCATN, pX, CONCATN, HH);
    }

    backcast_out_kernel<<<BNCNT, 256>>>(out);
    forecast_out_kernel<<<(BNCNT * HORZ * CC + 255) / 256, 256>>>(out + (size_t)MROWS * CONCATN);
}

// round 4
// speedup vs baseline: 1.7589x; 1.7589x over previous
#include <cuda_runtime.h>
#include <math.h>
#include <stdint.h>

#define NN 207
#define BB 32
#define TT 12
#define CC 2
#define HORZ 12
#define DID 64
#define HH 128
#define CONCATN 2560          // DID + TT + NN*TT
#define MROWS (BB*NN*CC)      // 13248
#define MPAD 13312            // 104 * 128
#define BNCNT (BB*NN)         // 6624
#define EPSILON_V 10.0f
#define EPS_V 1e-8f

// ---------------- scratch (device globals; no allocation) ----------------
__device__ float g_X[(size_t)MPAD * CONCATN];    // ~136MB
__device__ float g_H0[MPAD * HH];
__device__ float g_H1[MPAD * HH];
__device__ float g_F[MPAD * HORZ];
__device__ float g_hin[BNCNT * TT * CC];
__device__ float g_level[BNCNT * CC];
__device__ float g_tgf[BNCNT * HORZ];
__device__ float g_dp[NN * NN];
// transposed weights (N x K, K-major), tf32-rounded
__device__ float g_W0t[3 * HH * CONCATN];
__device__ float g_Wfct[3 * 2 * HH * HH];
__device__ float g_Wbt[3 * CONCATN * HH];

// ---------------- helpers ----------------
__device__ __forceinline__ uint32_t smem_u32(const void* p) {
    uint32_t a;
    asm("{ .reg .u64 t; cvta.to.shared.u64 t, %1; cvt.u32.u64 %0, t; }" : "=r"(a) : "l"(p));
    return a;
}
__device__ __forceinline__ float rna_tf32(float x) {
    float y;
    asm("cvt.rna.tf32.f32 %0, %1;" : "=f"(y) : "f"(x));
    return y;
}
#define CP_ASYNC16(s, g) asm volatile("cp.async.cg.shared.global [%0], [%1], 16;" :: "r"(s), "l"(g))
#define CP_COMMIT()      asm volatile("cp.async.commit_group;" ::: "memory")
#define CP_WAIT0()       asm volatile("cp.async.wait_group 0;" ::: "memory")
#define CP_WAIT1()       asm volatile("cp.async.wait_group 1;" ::: "memory")

__device__ __forceinline__ void mma_tf32(float* d, const uint32_t* a, const uint32_t* b) {
    asm volatile("mma.sync.aligned.m16n8k8.row.col.f32.tf32.tf32.f32 "
                 "{%0,%1,%2,%3}, {%4,%5,%6,%7}, {%8,%9}, {%0,%1,%2,%3};"
                 : "+f"(d[0]), "+f"(d[1]), "+f"(d[2]), "+f"(d[3])
                 : "r"(a[0]), "r"(a[1]), "r"(a[2]), "r"(a[3]), "r"(b[0]), "r"(b[1]));
}

// ---------------- time gates + h_in + level ----------------
__global__ void timegate_kernel(const float* __restrict__ hist,
                                const float* __restrict__ tod,
                                const float* __restrict__ emb,
                                const float* __restrict__ w1, const float* __restrict__ b1,
                                const float* __restrict__ w2, const float* __restrict__ b2,
                                const float* __restrict__ w3, const float* __restrict__ b3) {
    int bn = blockIdx.x;
    int n = bn % NN;
    __shared__ float sin_[DID + TT];
    __shared__ float stg[HH];
    __shared__ float stgb[TT];
    __shared__ float shin[TT * CC];
    int t = threadIdx.x;  // 128
    if (t < DID) sin_[t] = emb[n * DID + t];
    else if (t < DID + TT) sin_[t] = tod[bn * TT + (t - DID)];
    __syncthreads();
    float acc = b1[t];
#pragma unroll 4
    for (int i = 0; i < DID + TT; i++) acc += sin_[i] * w1[i * HH + t];
    stg[t] = fmaxf(acc, 0.f);
    __syncthreads();
    if (t < HORZ) {
        float a2 = b2[t], a3 = b3[t];
#pragma unroll 8
        for (int h = 0; h < HH; h++) {
            float v = stg[h];
            a2 += v * w2[h * HORZ + t];
            a3 += v * w3[h * TT + t];
        }
        g_tgf[bn * HORZ + t] = a2;
        stgb[t] = a3;
    }
    __syncthreads();
    if (t < TT * CC) {
        int tt = t >> 1, c = t & 1;
        float hv = hist[((size_t)bn * TT + tt) * CC + c] / (1.f + stgb[tt]);
        shin[t] = hv;
        g_hin[bn * TT * CC + t] = hv;
    }
    __syncthreads();
    if (t < CC) {
        float mx = -1e30f;
#pragma unroll
        for (int tt = 0; tt < TT; tt++) mx = fmaxf(mx, shin[tt * CC + t]);
        g_level[bn * CC + t] = mx;
    }
}

// ---------------- pairwise affinities ----------------
__global__ void dp_kernel(const float* __restrict__ emb) {
    int idx = blockIdx.x * blockDim.x + threadIdx.x;
    if (idx >= NN * NN) return;
    int i = idx / NN, j = idx % NN;
    float s = 0.f;
#pragma unroll 8
    for (int k = 0; k < DID; k++) s += emb[i * DID + k] * emb[j * DID + k];
    g_dp[idx] = expf(EPSILON_V * s);
}

// ---------------- zero the M-pad rows of X ----------------
__global__ void pad_zero_kernel() {
    int idx = blockIdx.x * blockDim.x + threadIdx.x;
    int total = (MPAD - MROWS) * CONCATN;
    if (idx < total) g_X[(size_t)MROWS * CONCATN + idx] = 0.f;
}

// ---------------- build X ----------------
__global__ void build_hist_kernel(const float* __restrict__ emb) {
    int bn = blockIdx.x;
    int b = bn / NN, n = bn % NN;
    __shared__ float sh[NN * TT * CC];
    __shared__ float sdp[NN];
    __shared__ float slvl[CC];
    int tid = threadIdx.x;
    for (int i = tid; i < NN * TT * CC; i += blockDim.x) sh[i] = g_hin[b * NN * TT * CC + i];
    for (int i = tid; i < NN; i += blockDim.x) sdp[i] = g_dp[n * NN + i];
    if (tid < CC) slvl[tid] = g_level[bn * CC + tid];
    __syncthreads();
    float lv0 = slvl[0], lv1 = slvl[1];
    float rl0 = 1.f / (lv0 + EPS_V), rl1 = 1.f / (lv1 + EPS_V);
    for (int idx = tid; idx < CC * CONCATN; idx += blockDim.x) {
        int c = idx / CONCATN;
        int k = idx - c * CONCATN;
        float lv = c ? lv1 : lv0;
        float rl = c ? rl1 : rl0;
        float val;
        if (k < TT) {
            val = sh[(n * TT + k) * CC + c] * rl;
        } else if (k < TT + NN * TT) {
            int m = k - TT;
            float a = sh[m * CC + c] * sdp[m / TT];
            val = fmaxf((a - lv) * rl, 0.f);
        } else {
            val = emb[n * DID + (k - TT - NN * TT)];
        }
        g_X[((size_t)bn * CC + c) * CONCATN + k] = val;
    }
}

// ---------------- weight transpose + tf32 round: out[n*K+k] = tf32(in[k*N+n]) ----------------
__global__ void transpose_kernel(const float* __restrict__ in, float* __restrict__ out,
                                 int K, int N) {
    __shared__ float t[32][33];
    int kb = blockIdx.x * 32, nb = blockIdx.y * 32;
    int x = threadIdx.x, y = threadIdx.y;  // 32 x 8
#pragma unroll
    for (int r = 0; r < 32; r += 8)
        t[y + r][x] = in[(size_t)(kb + y + r) * N + nb + x];
    __syncthreads();
#pragma unroll
    for (int r = 0; r < 32; r += 8)
        out[(size_t)(nb + y + r) * K + kb + x] = rna_tf32(t[x][y + r]);
}

// ---------------- tf32 mma.sync GEMM ----------------
// C(BM=128 x BN=64 tile) = A(MxK) @ Bt(NxK)^T, fp32 accum.
// 256 threads = 8 warps (2 warp-rows x 4 warp-cols), warp tile 64x16.
// EPI 0: Cout = relu(acc + bias) [ROUND: tf32-rounded]
// EPI 1: Cout = relu(Cout - (acc + bias)) in-place
// K % 32 == 0, M mult of 128, Nout mult of 64.
#define MM_BM 128
#define MM_BN 64
#define MM_BK 32
#define MM_STR 36                      // smem row stride (floats), conflict-free
#define MM_ASZ (MM_BM * MM_STR)        // 4608 floats per A buffer
#define MM_BSZ (MM_BN * MM_STR)        // 2304 floats per B buffer
#define MM_SMEM ((2 * (MM_ASZ + MM_BSZ)) * 4)   // 55296 bytes

template <int EPI, int ROUND>
__global__ void __launch_bounds__(256) gemm_mma_kernel(
        const float* __restrict__ A, const float* __restrict__ Bt,
        const float* __restrict__ bias, float* __restrict__ Cout,
        int Nout, int K) {
    extern __shared__ float sm[];
    float* sA = sm;                       // [2][MM_ASZ]
    float* sB = sm + 2 * MM_ASZ;          // [2][MM_BSZ]

    const int tid = threadIdx.x;
    const int wid = tid >> 5, lid = tid & 31;
    const int wm = wid >> 2, wn = wid & 3;      // warp row (0..1), warp col (0..3)
    const int g = lid >> 2, t = lid & 3;        // lane group / tig
    const int m0 = blockIdx.x * MM_BM, n0 = blockIdx.y * MM_BN;

    const float* gA = A + (size_t)m0 * K;
    const float* gB = Bt + (size_t)n0 * K;

    const uint32_t sA_u = smem_u32(sA);
    const uint32_t sB_u = smem_u32(sB);

    // per-thread cp.async source/dest precompute
    // A tile: 128 rows x 32 floats = 1024 16B-chunks; 4 per thread
    // B tile:  64 rows x 32 floats =  512 16B-chunks; 2 per thread
    auto load_tiles = [&](int k0, int buf) {
#pragma unroll
        for (int p = 0; p < 4; p++) {
            int idx = tid + (p << 8);
            int row = idx >> 3, kc = (idx & 7) << 2;
            uint32_t dst = sA_u + (buf * MM_ASZ + row * MM_STR + kc) * 4;
            CP_ASYNC16(dst, gA + (size_t)row * K + k0 + kc);
        }
#pragma unroll
        for (int p = 0; p < 2; p++) {
            int idx = tid + (p << 8);
            int row = idx >> 3, kc = (idx & 7) << 2;
            uint32_t dst = sB_u + (buf * MM_BSZ + row * MM_STR + kc) * 4;
            CP_ASYNC16(dst, gB + (size_t)row * K + k0 + kc);
        }
        CP_COMMIT();
    };

    float acc[4][2][4];
#pragma unroll
    for (int mf = 0; mf < 4; mf++)
#pragma unroll
        for (int nf = 0; nf < 2; nf++)
#pragma unroll
            for (int q = 0; q < 4; q++) acc[mf][nf][q] = 0.f;

    const int nch = K >> 5;
    load_tiles(0, 0);

    for (int ch = 0; ch < nch; ch++) {
        int buf = ch & 1;
        if (ch + 1 < nch) {
            load_tiles((ch + 1) << 5, buf ^ 1);
            CP_WAIT1();
        } else {
            CP_WAIT0();
        }
        __syncthreads();

        const uint32_t* uA = reinterpret_cast<const uint32_t*>(sA + buf * MM_ASZ);
        const uint32_t* uB = reinterpret_cast<const uint32_t*>(sB + buf * MM_BSZ);
#pragma unroll
        for (int ks = 0; ks < 4; ks++) {
            int kb = ks << 3;
            uint32_t af[4][4];
#pragma unroll
            for (int mf = 0; mf < 4; mf++) {
                int rb = (wm * 64 + mf * 16 + g) * MM_STR + kb + t;
                af[mf][0] = uA[rb];
                af[mf][1] = uA[rb + 8 * MM_STR];
                af[mf][2] = uA[rb + 4];
                af[mf][3] = uA[rb + 8 * MM_STR + 4];
            }
            uint32_t bf[2][2];
#pragma unroll
            for (int nf = 0; nf < 2; nf++) {
                int rb = (wn * 16 + nf * 8 + g) * MM_STR + kb + t;
                bf[nf][0] = uB[rb];
                bf[nf][1] = uB[rb + 4];
            }
#pragma unroll
            for (int mf = 0; mf < 4; mf++)
#pragma unroll
                for (int nf = 0; nf < 2; nf++)
                    mma_tf32(acc[mf][nf], af[mf], bf[nf]);
        }
        __syncthreads();
    }

    // epilogue: c0 -> (row, col), c1 -> (row, col+1), c2 -> (row+8, col), c3 -> (row+8, col+1)
#pragma unroll
    for (int mf = 0; mf < 4; mf++) {
#pragma unroll
        for (int nf = 0; nf < 2; nf++) {
            int row = m0 + wm * 64 + mf * 16 + g;
            int col = n0 + wn * 16 + nf * 8 + 2 * t;
            float2 bv = *reinterpret_cast<const float2*>(&bias[col]);
            float v0 = acc[mf][nf][0] + bv.x;
            float v1 = acc[mf][nf][1] + bv.y;
            float v2 = acc[mf][nf][2] + bv.x;
            float v3 = acc[mf][nf][3] + bv.y;
            float2* p0 = reinterpret_cast<float2*>(&Cout[(size_t)row * Nout + col]);
            float2* p1 = reinterpret_cast<float2*>(&Cout[(size_t)(row + 8) * Nout + col]);
            if (EPI == 0) {
                float2 r0, r1;
                r0.x = fmaxf(v0, 0.f); r0.y = fmaxf(v1, 0.f);
                r1.x = fmaxf(v2, 0.f); r1.y = fmaxf(v3, 0.f);
                if (ROUND) {
                    r0.x = rna_tf32(r0.x); r0.y = rna_tf32(r0.y);
                    r1.x = rna_tf32(r1.x); r1.y = rna_tf32(r1.y);
                }
                *p0 = r0; *p1 = r1;
            } else {
                float2 o0 = *p0, o1 = *p1;
                o0.x = fmaxf(o0.x - v0, 0.f); o0.y = fmaxf(o0.y - v1, 0.f);
                o1.x = fmaxf(o1.x - v2, 0.f); o1.y = fmaxf(o1.y - v3, 0.f);
                *p0 = o0; *p1 = o1;
            }
        }
    }
}

// ---------------- small GEMM for forecast head (Nout=12) ----------------
#define BM 64
#define BN 64
#define BKK 16

template <int EPI>   // 2 = store, 3 = accumulate
__global__ void sgemm_kernel(const float* __restrict__ A, const float* __restrict__ Bw,
                             const float* __restrict__ bias, float* __restrict__ Cout,
                             int M, int Nout, int K) {
    __shared__ float As[BKK][BM + 4];
    __shared__ float Bs[BKK][BN];
    int m0 = blockIdx.x * BM;
    int n0 = blockIdx.y * BN;
    int tid = threadIdx.x;
    int tx = tid & 15, ty = tid >> 4;
    float acc[4][4] = {};
    int arow = tid >> 2;
    int ac4 = (tid & 3) * 4;
    int bk = tid >> 4;
    int bn4 = (tid & 15) * 4;
    for (int k0 = 0; k0 < K; k0 += BKK) {
        float4 av = *reinterpret_cast<const float4*>(&A[(size_t)(m0 + arow) * K + k0 + ac4]);
        As[ac4 + 0][arow] = av.x;
        As[ac4 + 1][arow] = av.y;
        As[ac4 + 2][arow] = av.z;
        As[ac4 + 3][arow] = av.w;
#pragma unroll
        for (int j = 0; j < 4; j++) {
            int nc = n0 + bn4 + j;
            Bs[bk][bn4 + j] = (nc < Nout) ? Bw[(size_t)(k0 + bk) * Nout + nc] : 0.f;
        }
        __syncthreads();
#pragma unroll
        for (int k = 0; k < BKK; k++) {
            float4 a4 = *reinterpret_cast<const float4*>(&As[k][ty * 4]);
            float4 b4 = *reinterpret_cast<const float4*>(&Bs[k][tx * 4]);
            float a[4] = {a4.x, a4.y, a4.z, a4.w};
            float b[4] = {b4.x, b4.y, b4.z, b4.w};
#pragma unroll
            for (int i = 0; i < 4; i++)
#pragma unroll
                for (int j = 0; j < 4; j++) acc[i][j] += a[i] * b[j];
        }
        __syncthreads();
    }
#pragma unroll
    for (int i = 0; i < 4; i++) {
        int row = m0 + ty * 4 + i;
#pragma unroll
        for (int j = 0; j < 4; j++) {
            int col = n0 + tx * 4 + j;
            if (col < Nout) {
                float v = acc[i][j] + bias[col];
                size_t off = (size_t)row * Nout + col;
                if (EPI == 2) Cout[off] = v;
                else Cout[off] += v;
            }
        }
    }
}

// ---------------- outputs ----------------
__global__ void backcast_out_kernel(float* __restrict__ out) {
    int bn = blockIdx.x;
    const float* x0 = &g_X[(size_t)bn * CC * CONCATN];
    float2* o = reinterpret_cast<float2*>(out) + (size_t)bn * CONCATN;
    for (int k = threadIdx.x; k < CONCATN; k += blockDim.x) {
        float2 v;
        v.x = x0[k];
        v.y = x0[CONCATN + k];
        o[k] = v;
    }
}

__global__ void forecast_out_kernel(float* __restrict__ out) {
    int idx = blockIdx.x * blockDim.x + threadIdx.x;
    if (idx >= BNCNT * HORZ * CC) return;
    int c = idx & 1;
    int h = (idx >> 1) % HORZ;
    int bn = idx / (HORZ * CC);
    float v = g_F[((size_t)bn * CC + c) * HORZ + h];
    v *= g_level[bn * CC + c];
    v *= (1.f + g_tgf[bn * HORZ + h]);
    out[idx] = v;
}

// ---------------- launcher ----------------
extern "C" void kernel_launch(void* const* d_in, const int* in_sizes, int n_in,
                              void* d_out, int out_size) {
    const float* history = (const float*)d_in[0];
    const float* tod     = (const float*)d_in[1];
    const float* emb     = (const float*)d_in[2];
    const float* tg1_w = (const float*)d_in[3];
    const float* tg1_b = (const float*)d_in[4];
    const float* tg2_w = (const float*)d_in[5];
    const float* tg2_b = (const float*)d_in[6];
    const float* tg3_w = (const float*)d_in[7];
    const float* tg3_b = (const float*)d_in[8];
    const float* fc0_w = (const float*)d_in[9];
    const float* fc0_b = (const float*)d_in[10];
    const float* fc_w  = (const float*)d_in[11];
    const float* fc_b  = (const float*)d_in[12];
    const float* fore_w = (const float*)d_in[13];
    const float* fore_b = (const float*)d_in[14];
    const float* back_w = (const float*)d_in[15];
    const float* back_b = (const float*)d_in[16];
    float* out = (float*)d_out;

    float *pX, *pH0, *pH1, *pF, *pW0t, *pWfct, *pWbt;
    cudaGetSymbolAddress((void**)&pX, g_X);
    cudaGetSymbolAddress((void**)&pH0, g_H0);
    cudaGetSymbolAddress((void**)&pH1, g_H1);
    cudaGetSymbolAddress((void**)&pF, g_F);
    cudaGetSymbolAddress((void**)&pW0t, g_W0t);
    cudaGetSymbolAddress((void**)&pWfct, g_Wfct);
    cudaGetSymbolAddress((void**)&pWbt, g_Wbt);

    cudaFuncSetAttribute(gemm_mma_kernel<0, 1>, cudaFuncAttributeMaxDynamicSharedMemorySize, MM_SMEM);
    cudaFuncSetAttribute(gemm_mma_kernel<1, 0>, cudaFuncAttributeMaxDynamicSharedMemorySize, MM_SMEM);

    timegate_kernel<<<BNCNT, 128>>>(history, tod, emb, tg1_w, tg1_b, tg2_w, tg2_b, tg3_w, tg3_b);
    dp_kernel<<<(NN * NN + 255) / 256, 256>>>(emb);
    pad_zero_kernel<<<((MPAD - MROWS) * CONCATN + 255) / 256, 256>>>();

    // weight transposes (K x N -> N x K, tf32-rounded)
    for (int i = 0; i < 3; i++) {
        transpose_kernel<<<dim3(CONCATN / 32, HH / 32), dim3(32, 8)>>>(
            fc0_w + (size_t)i * CONCATN * HH, pW0t + (size_t)i * HH * CONCATN, CONCATN, HH);
        transpose_kernel<<<dim3(HH / 32, HH / 32), dim3(32, 8)>>>(
            fc_w + ((size_t)i * 2 + 0) * HH * HH, pWfct + ((size_t)i * 2 + 0) * HH * HH, HH, HH);
        transpose_kernel<<<dim3(HH / 32, HH / 32), dim3(32, 8)>>>(
            fc_w + ((size_t)i * 2 + 1) * HH * HH, pWfct + ((size_t)i * 2 + 1) * HH * HH, HH, HH);
        transpose_kernel<<<dim3(HH / 32, CONCATN / 32), dim3(32, 8)>>>(
            back_w + (size_t)i * HH * CONCATN, pWbt + (size_t)i * CONCATN * HH, HH, CONCATN);
    }

    build_hist_kernel<<<BNCNT, 256>>>(emb);

    const int GM = MPAD / MM_BM;   // 104
    for (int i = 0; i < 3; i++) {
        gemm_mma_kernel<0, 1><<<dim3(GM, HH / MM_BN), 256, MM_SMEM>>>(
            pX, pW0t + (size_t)i * HH * CONCATN, fc0_b + i * HH, pH0, HH, CONCATN);
        gemm_mma_kernel<0, 1><<<dim3(GM, HH / MM_BN), 256, MM_SMEM>>>(
            pH0, pWfct + ((size_t)i * 2 + 0) * HH * HH, fc_b + (i * 2 + 0) * HH, pH1, HH, HH);
        gemm_mma_kernel<0, 1><<<dim3(GM, HH / MM_BN), 256, MM_SMEM>>>(
            pH1, pWfct + ((size_t)i * 2 + 1) * HH * HH, fc_b + (i * 2 + 1) * HH, pH0, HH, HH);
        if (i == 0)
            sgemm_kernel<2><<<dim3(MPAD / BM, 1), 256>>>(
                pH0, fore_w + (size_t)i * HH * HORZ, fore_b + i * HORZ, pF, MPAD, HORZ, HH);
        else
            sgemm_kernel<3><<<dim3(MPAD / BM, 1), 256>>>(
                pH0, fore_w + (size_t)i * HH * HORZ, fore_b + i * HORZ, pF, MPAD, HORZ, HH);
        gemm_mma_kernel<1, 0><<<dim3(GM, CONCATN / MM_BN), 256, MM_SMEM>>>(
            pH0, pWbt + (size_t)i * CONCATN * HH, back_b + (size_t)i * CONCATN, pX, CONCATN, HH);
    }

    backcast_out_kernel<<<BNCNT, 256>>>(out);
    forecast_out_kernel<<<(BNCNT * HORZ * CC + 255) / 256, 256>>>(out + (size_t)MROWS * CONCATN);
}

// round 5
// speedup vs baseline: 3.1375x; 1.7838x over previous
#include <cuda_runtime.h>
#include <math.h>
#include <stdint.h>

#define NN 207
#define BB 32
#define TT 12
#define CC 2
#define HORZ 12
#define DID 64
#define HH 128
#define CONCATN 2560          // DID + TT + NN*TT
#define MROWS (BB*NN*CC)      // 13248
#define MPAD 13440            // 140*96 = 105*128, mult of 384
#define BNCNT (BB*NN)         // 6624
#define EPSILON_V 10.0f
#define EPS_V 1e-8f

// ---------------- scratch (device globals; no allocation) ----------------
__device__ float g_X[(size_t)MPAD * CONCATN];    // ~137MB
__device__ float g_H0[MPAD * HH];
__device__ float g_H1[MPAD * HH];
__device__ float g_F[MPAD * HORZ];
__device__ float g_hin[BNCNT * TT * CC];
__device__ float g_level[BNCNT * CC];
__device__ float g_tgf[BNCNT * HORZ];
__device__ float g_dp[NN * NN];
// transposed weights (N x K, K-major), tf32-rounded
__device__ float g_W0t[3 * HH * CONCATN];
__device__ float g_Wfct[3 * 2 * HH * HH];
__device__ float g_Wbt[3 * CONCATN * HH];

// ---------------- helpers ----------------
__device__ __forceinline__ uint32_t smem_u32(const void* p) {
    uint32_t a;
    asm("{ .reg .u64 t; cvta.to.shared.u64 t, %1; cvt.u32.u64 %0, t; }" : "=r"(a) : "l"(p));
    return a;
}
__device__ __forceinline__ float rna_tf32(float x) {
    float y;
    asm("cvt.rna.tf32.f32 %0, %1;" : "=f"(y) : "f"(x));
    return y;
}
#define CP_ASYNC16(s, g) asm volatile("cp.async.cg.shared.global [%0], [%1], 16;" :: "r"(s), "l"(g))
#define CP_COMMIT()      asm volatile("cp.async.commit_group;" ::: "memory")
#define CP_WAIT(n)       asm volatile("cp.async.wait_group %0;" :: "n"(n) : "memory")

__device__ __forceinline__ void mma_tf32(float* d, const uint32_t* a, const uint32_t* b) {
    asm volatile("mma.sync.aligned.m16n8k8.row.col.f32.tf32.tf32.f32 "
                 "{%0,%1,%2,%3}, {%4,%5,%6,%7}, {%8,%9}, {%0,%1,%2,%3};"
                 : "+f"(d[0]), "+f"(d[1]), "+f"(d[2]), "+f"(d[3])
                 : "r"(a[0]), "r"(a[1]), "r"(a[2]), "r"(a[3]), "r"(b[0]), "r"(b[1]));
}

// ---------------- time gates + h_in + level ----------------
__global__ void timegate_kernel(const float* __restrict__ hist,
                                const float* __restrict__ tod,
                                const float* __restrict__ emb,
                                const float* __restrict__ w1, const float* __restrict__ b1,
                                const float* __restrict__ w2, const float* __restrict__ b2,
                                const float* __restrict__ w3, const float* __restrict__ b3) {
    int bn = blockIdx.x;
    int n = bn % NN;
    __shared__ float sin_[DID + TT];
    __shared__ float stg[HH];
    __shared__ float stgb[TT];
    __shared__ float shin[TT * CC];
    int t = threadIdx.x;  // 128
    if (t < DID) sin_[t] = emb[n * DID + t];
    else if (t < DID + TT) sin_[t] = tod[bn * TT + (t - DID)];
    __syncthreads();
    float acc = b1[t];
#pragma unroll 4
    for (int i = 0; i < DID + TT; i++) acc += sin_[i] * w1[i * HH + t];
    stg[t] = fmaxf(acc, 0.f);
    __syncthreads();
    if (t < HORZ) {
        float a2 = b2[t], a3 = b3[t];
#pragma unroll 8
        for (int h = 0; h < HH; h++) {
            float v = stg[h];
            a2 += v * w2[h * HORZ + t];
            a3 += v * w3[h * TT + t];
        }
        g_tgf[bn * HORZ + t] = a2;
        stgb[t] = a3;
    }
    __syncthreads();
    if (t < TT * CC) {
        int tt = t >> 1, c = t & 1;
        float hv = hist[((size_t)bn * TT + tt) * CC + c] / (1.f + stgb[tt]);
        shin[t] = hv;
        g_hin[bn * TT * CC + t] = hv;
    }
    __syncthreads();
    if (t < CC) {
        float mx = -1e30f;
#pragma unroll
        for (int tt = 0; tt < TT; tt++) mx = fmaxf(mx, shin[tt * CC + t]);
        g_level[bn * CC + t] = mx;
    }
}

// ---------------- pairwise affinities ----------------
__global__ void dp_kernel(const float* __restrict__ emb) {
    int idx = blockIdx.x * blockDim.x + threadIdx.x;
    if (idx >= NN * NN) return;
    int i = idx / NN, j = idx % NN;
    float s = 0.f;
#pragma unroll 8
    for (int k = 0; k < DID; k++) s += emb[i * DID + k] * emb[j * DID + k];
    g_dp[idx] = expf(EPSILON_V * s);
}

// ---------------- zero the M-pad rows of X ----------------
__global__ void pad_zero_kernel() {
    int idx = blockIdx.x * blockDim.x + threadIdx.x;
    int total = (MPAD - MROWS) * CONCATN;
    if (idx < total) g_X[(size_t)MROWS * CONCATN + idx] = 0.f;
}

// ---------------- build X ----------------
__global__ void build_hist_kernel(const float* __restrict__ emb) {
    int bn = blockIdx.x;
    int b = bn / NN, n = bn % NN;
    __shared__ float sh[NN * TT * CC];
    __shared__ float sdp[NN];
    __shared__ float slvl[CC];
    int tid = threadIdx.x;
    for (int i = tid; i < NN * TT * CC; i += blockDim.x) sh[i] = g_hin[b * NN * TT * CC + i];
    for (int i = tid; i < NN; i += blockDim.x) sdp[i] = g_dp[n * NN + i];
    if (tid < CC) slvl[tid] = g_level[bn * CC + tid];
    __syncthreads();
    float lv0 = slvl[0], lv1 = slvl[1];
    float rl0 = 1.f / (lv0 + EPS_V), rl1 = 1.f / (lv1 + EPS_V);
    for (int idx = tid; idx < CC * CONCATN; idx += blockDim.x) {
        int c = idx / CONCATN;
        int k = idx - c * CONCATN;
        float lv = c ? lv1 : lv0;
        float rl = c ? rl1 : rl0;
        float val;
        if (k < TT) {
            val = sh[(n * TT + k) * CC + c] * rl;
        } else if (k < TT + NN * TT) {
            int m = k - TT;
            float a = sh[m * CC + c] * sdp[m / TT];
            val = fmaxf((a - lv) * rl, 0.f);
        } else {
            val = emb[n * DID + (k - TT - NN * TT)];
        }
        g_X[((size_t)bn * CC + c) * CONCATN + k] = val;
    }
}

// ---------------- batched weight transpose + tf32 round ----------------
// One launch handles all 12 matrices. 2016 blocks of 32x8.
__global__ void transpose_all_kernel(const float* __restrict__ fc0_w,
                                     const float* __restrict__ fc_w,
                                     const float* __restrict__ back_w) {
    __shared__ float t[32][33];
    int idx = blockIdx.x;
    int blk = idx / 672;
    int r = idx % 672;
    const float* in;
    float* out;
    int K, N, kb, nb;
    if (r < 320) {
        in = fc0_w + (size_t)blk * CONCATN * HH;
        out = g_W0t + (size_t)blk * HH * CONCATN;
        K = CONCATN; N = HH; kb = (r % 80) * 32; nb = (r / 80) * 32;
    } else if (r < 336) {
        r -= 320;
        in = fc_w + ((size_t)blk * 2 + 0) * HH * HH;
        out = g_Wfct + ((size_t)blk * 2 + 0) * HH * HH;
        K = HH; N = HH; kb = (r % 4) * 32; nb = (r / 4) * 32;
    } else if (r < 352) {
        r -= 336;
        in = fc_w + ((size_t)blk * 2 + 1) * HH * HH;
        out = g_Wfct + ((size_t)blk * 2 + 1) * HH * HH;
        K = HH; N = HH; kb = (r % 4) * 32; nb = (r / 4) * 32;
    } else {
        r -= 352;
        in = back_w + (size_t)blk * HH * CONCATN;
        out = g_Wbt + (size_t)blk * CONCATN * HH;
        K = HH; N = CONCATN; kb = (r % 4) * 32; nb = (r / 4) * 32;
    }
    int x = threadIdx.x, y = threadIdx.y;  // 32 x 8
#pragma unroll
    for (int rr = 0; rr < 32; rr += 8)
        t[y + rr][x] = in[(size_t)(kb + y + rr) * N + nb + x];
    __syncthreads();
#pragma unroll
    for (int rr = 0; rr < 32; rr += 8)
        out[(size_t)(nb + y + rr) * K + kb + x] = rna_tf32(t[x][y + rr]);
}

// ---------------- tf32 mma.sync GEMM ----------------
// C(BM=96 x BN=128 tile) = A(MxK) @ Bt(NxK)^T, fp32 accum, 3-stage cp.async.
// 256 threads = 8 warps (2 x 4), warp tile 48x32 (mf=3, nf=4 m16n8k8 frags).
// EPI 0: Cout = relu(acc + bias), tf32-rounded if ROUND
// EPI 1: Cout = relu(Cout - (acc + bias)) in-place (Xold == Cout)
// EPI 3: out-fused backcast: Cout(=d_out, interleaved) = relu(Xold - v), row<MROWS
// K % 32 == 0, M mult of 96, Nout mult of 128 (Nout = stride of A-producer output).
#define G_BM 96
#define G_BN 128
#define G_STR 36
#define G_ATS (G_BM * G_STR)           // 3456 floats
#define G_BTS (G_BN * G_STR)           // 4608 floats
#define G_STAGE (G_ATS + G_BTS)        // 8064 floats per stage
#define G_SMEM (3 * G_STAGE * 4)       // 96768 bytes

template <int EPI, int ROUND>
__global__ void __launch_bounds__(256) gemm_mma_kernel(
        const float* __restrict__ A, const float* __restrict__ Bt,
        const float* __restrict__ bias, float* __restrict__ Cout,
        const float* __restrict__ Xold, int Nout, int K) {
    extern __shared__ float sm[];
    const int tid = threadIdx.x;
    const int wid = tid >> 5, lid = tid & 31;
    const int wm = wid >> 2, wn = wid & 3;      // warp row (0..1), warp col (0..3)
    const int g = lid >> 2, t = lid & 3;
    const int m0 = blockIdx.x * G_BM, n0 = blockIdx.y * G_BN;

    const float* gA = A + (size_t)m0 * K;
    const float* gB = Bt + (size_t)n0 * K;
    const uint32_t sm_u = smem_u32(sm);

    auto load_tiles = [&](int k0, int st) {
        uint32_t base = sm_u + st * G_STAGE * 4;
#pragma unroll
        for (int p = 0; p < 3; p++) {          // A: 96x32 = 768 float4
            int idx = tid + (p << 8);
            int row = idx >> 3, kc = (idx & 7) << 2;
            CP_ASYNC16(base + (row * G_STR + kc) * 4, gA + (size_t)row * K + k0 + kc);
        }
#pragma unroll
        for (int p = 0; p < 4; p++) {          // B: 128x32 = 1024 float4
            int idx = tid + (p << 8);
            int row = idx >> 3, kc = (idx & 7) << 2;
            CP_ASYNC16(base + (G_ATS + row * G_STR + kc) * 4, gB + (size_t)row * K + k0 + kc);
        }
        CP_COMMIT();
    };

    float acc[3][4][4];
#pragma unroll
    for (int mf = 0; mf < 3; mf++)
#pragma unroll
        for (int nf = 0; nf < 4; nf++)
#pragma unroll
            for (int q = 0; q < 4; q++) acc[mf][nf][q] = 0.f;

    const int nch = K >> 5;
    load_tiles(0, 0);
    if (nch > 1) load_tiles(32, 1);

    for (int ch = 0; ch < nch; ch++) {
        int st = ch % 3;
        if (ch + 2 < nch) {
            load_tiles((ch + 2) << 5, (ch + 2) % 3);
            CP_WAIT(2);
        } else if (ch + 1 < nch) {
            CP_WAIT(1);
        } else {
            CP_WAIT(0);
        }
        __syncthreads();

        const uint32_t* uA = reinterpret_cast<const uint32_t*>(sm + st * G_STAGE);
        const uint32_t* uB = reinterpret_cast<const uint32_t*>(sm + st * G_STAGE + G_ATS);
#pragma unroll
        for (int ks = 0; ks < 4; ks++) {
            int kb = ks << 3;
            uint32_t af[3][4];
#pragma unroll
            for (int mf = 0; mf < 3; mf++) {
                int rb = (wm * 48 + mf * 16 + g) * G_STR + kb + t;
                af[mf][0] = uA[rb];
                af[mf][1] = uA[rb + 8 * G_STR];
                af[mf][2] = uA[rb + 4];
                af[mf][3] = uA[rb + 8 * G_STR + 4];
            }
            uint32_t bf[4][2];
#pragma unroll
            for (int nf = 0; nf < 4; nf++) {
                int rb = (wn * 32 + nf * 8 + g) * G_STR + kb + t;
                bf[nf][0] = uB[rb];
                bf[nf][1] = uB[rb + 4];
            }
#pragma unroll
            for (int mf = 0; mf < 3; mf++)
#pragma unroll
                for (int nf = 0; nf < 4; nf++)
                    mma_tf32(acc[mf][nf], af[mf], bf[nf]);
        }
        __syncthreads();
    }

    // epilogue
#pragma unroll
    for (int mf = 0; mf < 3; mf++) {
#pragma unroll
        for (int nf = 0; nf < 4; nf++) {
            int row = m0 + wm * 48 + mf * 16 + g;
            int col = n0 + wn * 32 + nf * 8 + 2 * t;
            float2 bv = *reinterpret_cast<const float2*>(&bias[col]);
            float v0 = acc[mf][nf][0] + bv.x;
            float v1 = acc[mf][nf][1] + bv.y;
            float v2 = acc[mf][nf][2] + bv.x;
            float v3 = acc[mf][nf][3] + bv.y;
            if (EPI == 0) {
                float2 r0, r1;
                r0.x = fmaxf(v0, 0.f); r0.y = fmaxf(v1, 0.f);
                r1.x = fmaxf(v2, 0.f); r1.y = fmaxf(v3, 0.f);
                if (ROUND) {
                    r0.x = rna_tf32(r0.x); r0.y = rna_tf32(r0.y);
                    r1.x = rna_tf32(r1.x); r1.y = rna_tf32(r1.y);
                }
                *reinterpret_cast<float2*>(&Cout[(size_t)row * Nout + col]) = r0;
                *reinterpret_cast<float2*>(&Cout[(size_t)(row + 8) * Nout + col]) = r1;
            } else if (EPI == 1) {
                float2* p0 = reinterpret_cast<float2*>(&Cout[(size_t)row * Nout + col]);
                float2* p1 = reinterpret_cast<float2*>(&Cout[(size_t)(row + 8) * Nout + col]);
                float2 o0 = *p0, o1 = *p1;
                o0.x = fmaxf(o0.x - v0, 0.f); o0.y = fmaxf(o0.y - v1, 0.f);
                o1.x = fmaxf(o1.x - v2, 0.f); o1.y = fmaxf(o1.y - v3, 0.f);
                *p0 = o0; *p1 = o1;
            } else {
                // final backcast: out[(row>>1)*2*CONCAT + col*2 + (row&1)]
                if (row < MROWS) {
                    float2 o0 = *reinterpret_cast<const float2*>(&Xold[(size_t)row * Nout + col]);
                    size_t ob = (size_t)(row >> 1) * (2 * CONCATN) + (size_t)col * 2 + (row & 1);
                    Cout[ob] = fmaxf(o0.x - v0, 0.f);
                    Cout[ob + 2] = fmaxf(o0.y - v1, 0.f);
                }
                int row2 = row + 8;
                if (row2 < MROWS) {
                    float2 o1 = *reinterpret_cast<const float2*>(&Xold[(size_t)row2 * Nout + col]);
                    size_t ob = (size_t)(row2 >> 1) * (2 * CONCATN) + (size_t)col * 2 + (row2 & 1);
                    Cout[ob] = fmaxf(o1.x - v2, 0.f);
                    Cout[ob + 2] = fmaxf(o1.y - v3, 0.f);
                }
            }
        }
    }
}

// ---------------- small GEMM for forecast head (Nout=12) ----------------
#define BM 64
#define BN 64
#define BKK 16

template <int EPI>   // 2 = store, 3 = accumulate
__global__ void sgemm_kernel(const float* __restrict__ A, const float* __restrict__ Bw,
                             const float* __restrict__ bias, float* __restrict__ Cout,
                             int M, int Nout, int K) {
    __shared__ float As[BKK][BM + 4];
    __shared__ float Bs[BKK][BN];
    int m0 = blockIdx.x * BM;
    int n0 = blockIdx.y * BN;
    int tid = threadIdx.x;
    int tx = tid & 15, ty = tid >> 4;
    float acc[4][4] = {};
    int arow = tid >> 2;
    int ac4 = (tid & 3) * 4;
    int bk = tid >> 4;
    int bn4 = (tid & 15) * 4;
    for (int k0 = 0; k0 < K; k0 += BKK) {
        float4 av = *reinterpret_cast<const float4*>(&A[(size_t)(m0 + arow) * K + k0 + ac4]);
        As[ac4 + 0][arow] = av.x;
        As[ac4 + 1][arow] = av.y;
        As[ac4 + 2][arow] = av.z;
        As[ac4 + 3][arow] = av.w;
#pragma unroll
        for (int j = 0; j < 4; j++) {
            int nc = n0 + bn4 + j;
            Bs[bk][bn4 + j] = (nc < Nout) ? Bw[(size_t)(k0 + bk) * Nout + nc] : 0.f;
        }
        __syncthreads();
#pragma unroll
        for (int k = 0; k < BKK; k++) {
            float4 a4 = *reinterpret_cast<const float4*>(&As[k][ty * 4]);
            float4 b4 = *reinterpret_cast<const float4*>(&Bs[k][tx * 4]);
            float a[4] = {a4.x, a4.y, a4.z, a4.w};
            float b[4] = {b4.x, b4.y, b4.z, b4.w};
#pragma unroll
            for (int i = 0; i < 4; i++)
#pragma unroll
                for (int j = 0; j < 4; j++) acc[i][j] += a[i] * b[j];
        }
        __syncthreads();
    }
#pragma unroll
    for (int i = 0; i < 4; i++) {
        int row = m0 + ty * 4 + i;
#pragma unroll
        for (int j = 0; j < 4; j++) {
            int col = n0 + tx * 4 + j;
            if (col < Nout) {
                float v = acc[i][j] + bias[col];
                size_t off = (size_t)row * Nout + col;
                if (EPI == 2) Cout[off] = v;
                else Cout[off] += v;
            }
        }
    }
}

// ---------------- forecast output ----------------
__global__ void forecast_out_kernel(float* __restrict__ out) {
    int idx = blockIdx.x * blockDim.x + threadIdx.x;
    if (idx >= BNCNT * HORZ * CC) return;
    int c = idx & 1;
    int h = (idx >> 1) % HORZ;
    int bn = idx / (HORZ * CC);
    float v = g_F[((size_t)bn * CC + c) * HORZ + h];
    v *= g_level[bn * CC + c];
    v *= (1.f + g_tgf[bn * HORZ + h]);
    out[idx] = v;
}

// ---------------- launcher ----------------
extern "C" void kernel_launch(void* const* d_in, const int* in_sizes, int n_in,
                              void* d_out, int out_size) {
    const float* history = (const float*)d_in[0];
    const float* tod     = (const float*)d_in[1];
    const float* emb     = (const float*)d_in[2];
    const float* tg1_w = (const float*)d_in[3];
    const float* tg1_b = (const float*)d_in[4];
    const float* tg2_w = (const float*)d_in[5];
    const float* tg2_b = (const float*)d_in[6];
    const float* tg3_w = (const float*)d_in[7];
    const float* tg3_b = (const float*)d_in[8];
    const float* fc0_w = (const float*)d_in[9];
    const float* fc0_b = (const float*)d_in[10];
    const float* fc_w  = (const float*)d_in[11];
    const float* fc_b  = (const float*)d_in[12];
    const float* fore_w = (const float*)d_in[13];
    const float* fore_b = (const float*)d_in[14];
    const float* back_w = (const float*)d_in[15];
    const float* back_b = (const float*)d_in[16];
    float* out = (float*)d_out;

    float *pX, *pH0, *pH1, *pF, *pW0t, *pWfct, *pWbt;
    cudaGetSymbolAddress((void**)&pX, g_X);
    cudaGetSymbolAddress((void**)&pH0, g_H0);
    cudaGetSymbolAddress((void**)&pH1, g_H1);
    cudaGetSymbolAddress((void**)&pF, g_F);
    cudaGetSymbolAddress((void**)&pW0t, g_W0t);
    cudaGetSymbolAddress((void**)&pWfct, g_Wfct);
    cudaGetSymbolAddress((void**)&pWbt, g_Wbt);

    cudaFuncSetAttribute(gemm_mma_kernel<0, 1>, cudaFuncAttributeMaxDynamicSharedMemorySize, G_SMEM);
    cudaFuncSetAttribute(gemm_mma_kernel<1, 0>, cudaFuncAttributeMaxDynamicSharedMemorySize, G_SMEM);
    cudaFuncSetAttribute(gemm_mma_kernel<3, 0>, cudaFuncAttributeMaxDynamicSharedMemorySize, G_SMEM);

    timegate_kernel<<<BNCNT, 128>>>(history, tod, emb, tg1_w, tg1_b, tg2_w, tg2_b, tg3_w, tg3_b);
    dp_kernel<<<(NN * NN + 255) / 256, 256>>>(emb);
    pad_zero_kernel<<<((MPAD - MROWS) * CONCATN + 255) / 256, 256>>>();
    transpose_all_kernel<<<2016, dim3(32, 8)>>>(fc0_w, fc_w, back_w);
    build_hist_kernel<<<BNCNT, 256>>>(emb);

    const int GMX = MPAD / G_BM;   // 140
    for (int i = 0; i < 3; i++) {
        gemm_mma_kernel<0, 1><<<dim3(GMX, 1), 256, G_SMEM>>>(
            pX, pW0t + (size_t)i * HH * CONCATN, fc0_b + i * HH, pH0, pH0, HH, CONCATN);
        gemm_mma_kernel<0, 1><<<dim3(GMX, 1), 256, G_SMEM>>>(
            pH0, pWfct + ((size_t)i * 2 + 0) * HH * HH, fc_b + (i * 2 + 0) * HH, pH1, pH1, HH, HH);
        gemm_mma_kernel<0, 1><<<dim3(GMX, 1), 256, G_SMEM>>>(
            pH1, pWfct + ((size_t)i * 2 + 1) * HH * HH, fc_b + (i * 2 + 1) * HH, pH0, pH0, HH, HH);
        if (i == 0)
            sgemm_kernel<2><<<dim3(MPAD / BM, 1), 256>>>(
                pH0, fore_w + (size_t)i * HH * HORZ, fore_b + i * HORZ, pF, MPAD, HORZ, HH);
        else
            sgemm_kernel<3><<<dim3(MPAD / BM, 1), 256>>>(
                pH0, fore_w + (size_t)i * HH * HORZ, fore_b + i * HORZ, pF, MPAD, HORZ, HH);
        if (i < 2)
            gemm_mma_kernel<1, 0><<<dim3(GMX, CONCATN / G_BN), 256, G_SMEM>>>(
                pH0, pWbt + (size_t)i * CONCATN * HH, back_b + (size_t)i * CONCATN, pX, pX, CONCATN, HH);
        else
            gemm_mma_kernel<3, 0><<<dim3(GMX, CONCATN / G_BN), 256, G_SMEM>>>(
                pH0, pWbt + (size_t)i * CONCATN * HH, back_b + (size_t)i * CONCATN, out, pX, CONCATN, HH);
    }

    forecast_out_kernel<<<(BNCNT * HORZ * CC + 255) / 256, 256>>>(out + (size_t)MROWS * CONCATN);
}

// round 6
// speedup vs baseline: 3.5006x; 1.1157x over previous
#include <cuda_runtime.h>
#include <cuda_fp16.h>
#include <math.h>
#include <stdint.h>

#define NN 207
#define BB 32
#define TT 12
#define CC 2
#define HORZ 12
#define DID 64
#define HH 128
#define CONCATN 2560          // DID + TT + NN*TT
#define MROWS (BB*NN*CC)      // 13248
#define MPAD 13440            // 140*96
#define BNCNT (BB*NN)         // 6624
#define EPSILON_V 10.0f
#define EPS_V 1e-8f

// ---------------- scratch (device globals; no allocation) ----------------
__device__ float g_X[(size_t)MPAD * CONCATN];    // ~137MB
__device__ float g_H0[MPAD * HH];
__device__ float g_H1[MPAD * HH];
__device__ float g_F[MPAD * HORZ];
__device__ float g_hin[BNCNT * TT * CC];
__device__ float g_level[BNCNT * CC];
__device__ float g_tgf[BNCNT * HORZ];
__device__ float g_dp[NN * NN];
// transposed weights (N x K, K-major), fp16
__device__ __half g_W0t[3 * HH * CONCATN];
__device__ __half g_Wfct[3 * 2 * HH * HH];
__device__ __half g_Wbt[3 * CONCATN * HH];

// ---------------- helpers ----------------
__device__ __forceinline__ uint32_t smem_u32(const void* p) {
    uint32_t a;
    asm("{ .reg .u64 t; cvta.to.shared.u64 t, %1; cvt.u32.u64 %0, t; }" : "=r"(a) : "l"(p));
    return a;
}
__device__ __forceinline__ uint32_t pack_f16x2(float lo, float hi) {
    uint32_t r;
    asm("cvt.rn.f16x2.f32 %0, %1, %2;" : "=r"(r) : "f"(hi), "f"(lo));
    return r;
}
#define CP_ASYNC16(s, g) asm volatile("cp.async.cg.shared.global [%0], [%1], 16;" :: "r"(s), "l"(g))
#define CP_COMMIT()      asm volatile("cp.async.commit_group;" ::: "memory")
#define CP_WAIT(n)       asm volatile("cp.async.wait_group %0;" :: "n"(n) : "memory")

__device__ __forceinline__ void mma_f16(float* d, const uint32_t* a, const uint32_t* b) {
    asm volatile("mma.sync.aligned.m16n8k16.row.col.f32.f16.f16.f32 "
                 "{%0,%1,%2,%3}, {%4,%5,%6,%7}, {%8,%9}, {%0,%1,%2,%3};"
                 : "+f"(d[0]), "+f"(d[1]), "+f"(d[2]), "+f"(d[3])
                 : "r"(a[0]), "r"(a[1]), "r"(a[2]), "r"(a[3]), "r"(b[0]), "r"(b[1]));
}

// ---------------- time gates + h_in + level ----------------
__global__ void timegate_kernel(const float* __restrict__ hist,
                                const float* __restrict__ tod,
                                const float* __restrict__ emb,
                                const float* __restrict__ w1, const float* __restrict__ b1,
                                const float* __restrict__ w2, const float* __restrict__ b2,
                                const float* __restrict__ w3, const float* __restrict__ b3) {
    int bn = blockIdx.x;
    int n = bn % NN;
    __shared__ float sin_[DID + TT];
    __shared__ float stg[HH];
    __shared__ float stgb[TT];
    __shared__ float shin[TT * CC];
    int t = threadIdx.x;  // 128
    if (t < DID) sin_[t] = emb[n * DID + t];
    else if (t < DID + TT) sin_[t] = tod[bn * TT + (t - DID)];
    __syncthreads();
    float acc = b1[t];
#pragma unroll 4
    for (int i = 0; i < DID + TT; i++) acc += sin_[i] * w1[i * HH + t];
    stg[t] = fmaxf(acc, 0.f);
    __syncthreads();
    if (t < HORZ) {
        float a2 = b2[t], a3 = b3[t];
#pragma unroll 8
        for (int h = 0; h < HH; h++) {
            float v = stg[h];
            a2 += v * w2[h * HORZ + t];
            a3 += v * w3[h * TT + t];
        }
        g_tgf[bn * HORZ + t] = a2;
        stgb[t] = a3;
    }
    __syncthreads();
    if (t < TT * CC) {
        int tt = t >> 1, c = t & 1;
        float hv = hist[((size_t)bn * TT + tt) * CC + c] / (1.f + stgb[tt]);
        shin[t] = hv;
        g_hin[bn * TT * CC + t] = hv;
    }
    __syncthreads();
    if (t < CC) {
        float mx = -1e30f;
#pragma unroll
        for (int tt = 0; tt < TT; tt++) mx = fmaxf(mx, shin[tt * CC + t]);
        g_level[bn * CC + t] = mx;
    }
}

// ---------------- pairwise affinities ----------------
__global__ void dp_kernel(const float* __restrict__ emb) {
    int idx = blockIdx.x * blockDim.x + threadIdx.x;
    if (idx >= NN * NN) return;
    int i = idx / NN, j = idx % NN;
    float s = 0.f;
#pragma unroll 8
    for (int k = 0; k < DID; k++) s += emb[i * DID + k] * emb[j * DID + k];
    g_dp[idx] = expf(EPSILON_V * s);
}

// ---------------- zero the M-pad rows of X ----------------
__global__ void pad_zero_kernel() {
    int idx = blockIdx.x * blockDim.x + threadIdx.x;
    int total = (MPAD - MROWS) * CONCATN;
    if (idx < total) g_X[(size_t)MROWS * CONCATN + idx] = 0.f;
}

// ---------------- build X (division-free, vectorized) ----------------
__global__ void build_hist_kernel(const float* __restrict__ emb) {
    int bn = blockIdx.x;
    int b = bn / NN, n = bn % NN;
    __shared__ float sh[NN * TT * CC];   // 4968
    __shared__ float sdp[NN];
    __shared__ float slvl[CC];
    int tid = threadIdx.x;               // 256
    for (int i = tid; i < NN * TT * CC; i += 256) sh[i] = g_hin[b * NN * TT * CC + i];
    for (int i = tid; i < NN; i += 256) sdp[i] = g_dp[n * NN + i];
    if (tid < CC) slvl[tid] = g_level[bn * CC + tid];
    __syncthreads();
    float lv[2] = {slvl[0], slvl[1]};
    float rl[2] = {1.f / (lv[0] + EPS_V), 1.f / (lv[1] + EPS_V)};
    float* xb = &g_X[(size_t)bn * CC * CONCATN];

    // middle region: (src, c) pairs, 12 values each, 3 float4 stores
    for (int pair = tid; pair < 2 * NN; pair += 256) {
        int c = (pair >= NN) ? 1 : 0;
        int src = pair - NN * c;
        float d = sdp[src];
        float l = lv[c], r = rl[c];
        float v[12];
#pragma unroll
        for (int t = 0; t < 12; t++) {
            float a = sh[(src * 12 + t) * 2 + c] * d;
            v[t] = fmaxf((a - l) * r, 0.f);
        }
        float* dst = xb + (size_t)c * CONCATN + 12 + src * 12;
#pragma unroll
        for (int q = 0; q < 3; q++) {
            float4 f4;
            f4.x = v[q * 4]; f4.y = v[q * 4 + 1]; f4.z = v[q * 4 + 2]; f4.w = v[q * 4 + 3];
            *reinterpret_cast<float4*>(dst + q * 4) = f4;
        }
    }
    // history region (k < 12)
    if (tid < 24) {
        int c = tid >= 12 ? 1 : 0;
        int t = tid - 12 * c;
        xb[(size_t)c * CONCATN + t] = sh[(n * 12 + t) * 2 + c] * rl[c];
    }
    // emb region (k >= 2496)
    if (tid < 128) {
        int c = tid >> 6, d = tid & 63;
        xb[(size_t)c * CONCATN + (TT + NN * TT) + d] = emb[n * DID + d];
    }
}

// ---------------- batched weight transpose -> fp16 (N x K) ----------------
__global__ void transpose_all_kernel(const float* __restrict__ fc0_w,
                                     const float* __restrict__ fc_w,
                                     const float* __restrict__ back_w) {
    __shared__ float t[32][33];
    int idx = blockIdx.x;
    int blk = idx / 672;
    int r = idx % 672;
    const float* in;
    __half* out;
    int K, N, kb, nb;
    if (r < 320) {
        in = fc0_w + (size_t)blk * CONCATN * HH;
        out = g_W0t + (size_t)blk * HH * CONCATN;
        K = CONCATN; N = HH; kb = (r % 80) * 32; nb = (r / 80) * 32;
    } else if (r < 336) {
        r -= 320;
        in = fc_w + ((size_t)blk * 2 + 0) * HH * HH;
        out = g_Wfct + ((size_t)blk * 2 + 0) * HH * HH;
        K = HH; N = HH; kb = (r % 4) * 32; nb = (r / 4) * 32;
    } else if (r < 352) {
        r -= 336;
        in = fc_w + ((size_t)blk * 2 + 1) * HH * HH;
        out = g_Wfct + ((size_t)blk * 2 + 1) * HH * HH;
        K = HH; N = HH; kb = (r % 4) * 32; nb = (r / 4) * 32;
    } else {
        r -= 352;
        in = back_w + (size_t)blk * HH * CONCATN;
        out = g_Wbt + (size_t)blk * CONCATN * HH;
        K = HH; N = CONCATN; kb = (r % 4) * 32; nb = (r / 4) * 32;
    }
    int x = threadIdx.x, y = threadIdx.y;  // 32 x 8
#pragma unroll
    for (int rr = 0; rr < 32; rr += 8)
        t[y + rr][x] = in[(size_t)(kb + y + rr) * N + nb + x];
    __syncthreads();
#pragma unroll
    for (int rr = 0; rr < 32; rr += 8)
        out[(size_t)(nb + y + rr) * K + kb + x] = __float2half_rn(t[x][y + rr]);
}

// ---------------- fp16 mma.sync GEMM (fp32 A in gmem, fp16 weights) ----------------
// C(96 x 128 tile) = A(MxK fp32) @ Wt(NxK fp16)^T, fp32 accum, 3-stage cp.async.
// 256 threads = 8 warps (2x4), warp tile 48x32 (mf=3, nf=4 m16n8k16 frags).
// EPI 0: Cout = relu(acc + bias)
// EPI 1: Cout = relu(Cout - (acc + bias)) in-place (Xold == Cout)
// EPI 3: fused backcast: Cout(=d_out, interleaved) = relu(Xold - v), row < MROWS
#define G_BM 96
#define G_BN 128
#define SA_STR 40                        // floats per A smem row
#define SB_STR 40                        // halves per B smem row
#define A_STG_B (G_BM * SA_STR * 4)      // 15360 bytes
#define B_STG_B (G_BN * SB_STR * 2)      // 10240 bytes
#define STG_B (A_STG_B + B_STG_B)        // 25600 bytes
#define G_SMEM (3 * STG_B)               // 76800 bytes

template <int EPI>
__global__ void __launch_bounds__(256) gemm_mma_kernel(
        const float* __restrict__ A, const __half* __restrict__ Bt,
        const float* __restrict__ bias, float* __restrict__ Cout,
        const float* __restrict__ Xold, int Nout, int K) {
    extern __shared__ char smc[];
    const int tid = threadIdx.x;
    const int wid = tid >> 5, lid = tid & 31;
    const int wm = wid >> 2, wn = wid & 3;
    const int g = lid >> 2, t = lid & 3;
    const int m0 = blockIdx.x * G_BM, n0 = blockIdx.y * G_BN;

    const float* gA = A + (size_t)m0 * K;
    const __half* gB = Bt + (size_t)n0 * K;
    const uint32_t sm_u = smem_u32(smc);

    auto load_tiles = [&](int k0, int st) {
        uint32_t base = sm_u + st * STG_B;
#pragma unroll
        for (int p = 0; p < 3; p++) {       // A: 96 rows x 32 fp32 = 768 chunks
            int idx = tid + (p << 8);
            int row = idx >> 3, kc = (idx & 7) << 2;
            CP_ASYNC16(base + (row * SA_STR + kc) * 4, gA + (size_t)row * K + k0 + kc);
        }
        uint32_t baseB = base + A_STG_B;
#pragma unroll
        for (int p = 0; p < 2; p++) {       // B: 128 rows x 32 fp16 = 512 chunks
            int idx = tid + (p << 8);
            int row = idx >> 2, kh = (idx & 3) << 3;
            CP_ASYNC16(baseB + (row * SB_STR + kh) * 2, gB + (size_t)row * K + k0 + kh);
        }
        CP_COMMIT();
    };

    float acc[3][4][4];
#pragma unroll
    for (int mf = 0; mf < 3; mf++)
#pragma unroll
        for (int nf = 0; nf < 4; nf++)
#pragma unroll
            for (int q = 0; q < 4; q++) acc[mf][nf][q] = 0.f;

    const int nch = K >> 5;
    load_tiles(0, 0);
    if (nch > 1) load_tiles(32, 1);

    for (int ch = 0; ch < nch; ch++) {
        int st = ch % 3;
        if (ch + 2 < nch) {
            load_tiles((ch + 2) << 5, (ch + 2) % 3);
            CP_WAIT(2);
        } else if (ch + 1 < nch) {
            CP_WAIT(1);
        } else {
            CP_WAIT(0);
        }
        __syncthreads();

        const float* sA = reinterpret_cast<const float*>(smc + st * STG_B);
        const uint32_t* sB = reinterpret_cast<const uint32_t*>(smc + st * STG_B + A_STG_B);
#pragma unroll
        for (int ks = 0; ks < 2; ks++) {     // two k16 steps per 32-chunk
            int kb = ks << 4;
            uint32_t af[3][4];
#pragma unroll
            for (int mf = 0; mf < 3; mf++) {
                int r = wm * 48 + mf * 16 + g;
                float2 f0 = *reinterpret_cast<const float2*>(&sA[r * SA_STR + kb + 2 * t]);
                float2 f1 = *reinterpret_cast<const float2*>(&sA[(r + 8) * SA_STR + kb + 2 * t]);
                float2 f2 = *reinterpret_cast<const float2*>(&sA[r * SA_STR + kb + 8 + 2 * t]);
                float2 f3 = *reinterpret_cast<const float2*>(&sA[(r + 8) * SA_STR + kb + 8 + 2 * t]);
                af[mf][0] = pack_f16x2(f0.x, f0.y);
                af[mf][1] = pack_f16x2(f1.x, f1.y);
                af[mf][2] = pack_f16x2(f2.x, f2.y);
                af[mf][3] = pack_f16x2(f3.x, f3.y);
            }
            uint32_t bf[4][2];
#pragma unroll
            for (int nf = 0; nf < 4; nf++) {
                int n = wn * 32 + nf * 8 + g;
                bf[nf][0] = sB[n * (SB_STR / 2) + ks * 8 + t];
                bf[nf][1] = sB[n * (SB_STR / 2) + ks * 8 + 4 + t];
            }
#pragma unroll
            for (int mf = 0; mf < 3; mf++)
#pragma unroll
                for (int nf = 0; nf < 4; nf++)
                    mma_f16(acc[mf][nf], af[mf], bf[nf]);
        }
        __syncthreads();
    }

    // epilogue
#pragma unroll
    for (int mf = 0; mf < 3; mf++) {
#pragma unroll
        for (int nf = 0; nf < 4; nf++) {
            int row = m0 + wm * 48 + mf * 16 + g;
            int col = n0 + wn * 32 + nf * 8 + 2 * t;
            float2 bv = *reinterpret_cast<const float2*>(&bias[col]);
            float v0 = acc[mf][nf][0] + bv.x;
            float v1 = acc[mf][nf][1] + bv.y;
            float v2 = acc[mf][nf][2] + bv.x;
            float v3 = acc[mf][nf][3] + bv.y;
            if (EPI == 0) {
                float2 r0, r1;
                r0.x = fmaxf(v0, 0.f); r0.y = fmaxf(v1, 0.f);
                r1.x = fmaxf(v2, 0.f); r1.y = fmaxf(v3, 0.f);
                *reinterpret_cast<float2*>(&Cout[(size_t)row * Nout + col]) = r0;
                *reinterpret_cast<float2*>(&Cout[(size_t)(row + 8) * Nout + col]) = r1;
            } else if (EPI == 1) {
                float2* p0 = reinterpret_cast<float2*>(&Cout[(size_t)row * Nout + col]);
                float2* p1 = reinterpret_cast<float2*>(&Cout[(size_t)(row + 8) * Nout + col]);
                float2 o0 = *p0, o1 = *p1;
                o0.x = fmaxf(o0.x - v0, 0.f); o0.y = fmaxf(o0.y - v1, 0.f);
                o1.x = fmaxf(o1.x - v2, 0.f); o1.y = fmaxf(o1.y - v3, 0.f);
                *p0 = o0; *p1 = o1;
            } else {
                if (row < MROWS) {
                    float2 o0 = *reinterpret_cast<const float2*>(&Xold[(size_t)row * Nout + col]);
                    size_t ob = (size_t)(row >> 1) * (2 * CONCATN) + (size_t)col * 2 + (row & 1);
                    Cout[ob] = fmaxf(o0.x - v0, 0.f);
                    Cout[ob + 2] = fmaxf(o0.y - v1, 0.f);
                }
                int row2 = row + 8;
                if (row2 < MROWS) {
                    float2 o1 = *reinterpret_cast<const float2*>(&Xold[(size_t)row2 * Nout + col]);
                    size_t ob = (size_t)(row2 >> 1) * (2 * CONCATN) + (size_t)col * 2 + (row2 & 1);
                    Cout[ob] = fmaxf(o1.x - v2, 0.f);
                    Cout[ob + 2] = fmaxf(o1.y - v3, 0.f);
                }
            }
        }
    }
}

// ---------------- small GEMM for forecast head (Nout=12) ----------------
#define BM 64
#define BN 64
#define BKK 16

template <int EPI>   // 2 = store, 3 = accumulate
__global__ void sgemm_kernel(const float* __restrict__ A, const float* __restrict__ Bw,
                             const float* __restrict__ bias, float* __restrict__ Cout,
                             int M, int Nout, int K) {
    __shared__ float As[BKK][BM + 4];
    __shared__ float Bs[BKK][BN];
    int m0 = blockIdx.x * BM;
    int n0 = blockIdx.y * BN;
    int tid = threadIdx.x;
    int tx = tid & 15, ty = tid >> 4;
    float acc[4][4] = {};
    int arow = tid >> 2;
    int ac4 = (tid & 3) * 4;
    int bk = tid >> 4;
    int bn4 = (tid & 15) * 4;
    for (int k0 = 0; k0 < K; k0 += BKK) {
        float4 av = *reinterpret_cast<const float4*>(&A[(size_t)(m0 + arow) * K + k0 + ac4]);
        As[ac4 + 0][arow] = av.x;
        As[ac4 + 1][arow] = av.y;
        As[ac4 + 2][arow] = av.z;
        As[ac4 + 3][arow] = av.w;
#pragma unroll
        for (int j = 0; j < 4; j++) {
            int nc = n0 + bn4 + j;
            Bs[bk][bn4 + j] = (nc < Nout) ? Bw[(size_t)(k0 + bk) * Nout + nc] : 0.f;
        }
        __syncthreads();
#pragma unroll
        for (int k = 0; k < BKK; k++) {
            float4 a4 = *reinterpret_cast<const float4*>(&As[k][ty * 4]);
            float4 b4 = *reinterpret_cast<const float4*>(&Bs[k][tx * 4]);
            float a[4] = {a4.x, a4.y, a4.z, a4.w};
            float b[4] = {b4.x, b4.y, b4.z, b4.w};
#pragma unroll
            for (int i = 0; i < 4; i++)
#pragma unroll
                for (int j = 0; j < 4; j++) acc[i][j] += a[i] * b[j];
        }
        __syncthreads();
    }
#pragma unroll
    for (int i = 0; i < 4; i++) {
        int row = m0 + ty * 4 + i;
#pragma unroll
        for (int j = 0; j < 4; j++) {
            int col = n0 + tx * 4 + j;
            if (col < Nout) {
                float v = acc[i][j] + bias[col];
                size_t off = (size_t)row * Nout + col;
                if (EPI == 2) Cout[off] = v;
                else Cout[off] += v;
            }
        }
    }
}

// ---------------- forecast output ----------------
__global__ void forecast_out_kernel(float* __restrict__ out) {
    int idx = blockIdx.x * blockDim.x + threadIdx.x;
    if (idx >= BNCNT * HORZ * CC) return;
    int c = idx & 1;
    int h = (idx >> 1) % HORZ;
    int bn = idx / (HORZ * CC);
    float v = g_F[((size_t)bn * CC + c) * HORZ + h];
    v *= g_level[bn * CC + c];
    v *= (1.f + g_tgf[bn * HORZ + h]);
    out[idx] = v;
}

// ---------------- launcher ----------------
extern "C" void kernel_launch(void* const* d_in, const int* in_sizes, int n_in,
                              void* d_out, int out_size) {
    const float* history = (const float*)d_in[0];
    const float* tod     = (const float*)d_in[1];
    const float* emb     = (const float*)d_in[2];
    const float* tg1_w = (const float*)d_in[3];
    const float* tg1_b = (const float*)d_in[4];
    const float* tg2_w = (const float*)d_in[5];
    const float* tg2_b = (const float*)d_in[6];
    const float* tg3_w = (const float*)d_in[7];
    const float* tg3_b = (const float*)d_in[8];
    const float* fc0_w = (const float*)d_in[9];
    const float* fc0_b = (const float*)d_in[10];
    const float* fc_w  = (const float*)d_in[11];
    const float* fc_b  = (const float*)d_in[12];
    const float* fore_w = (const float*)d_in[13];
    const float* fore_b = (const float*)d_in[14];
    const float* back_w = (const float*)d_in[15];
    const float* back_b = (const float*)d_in[16];
    float* out = (float*)d_out;

    float *pX, *pH0, *pH1, *pF;
    __half *pW0t, *pWfct, *pWbt;
    cudaGetSymbolAddress((void**)&pX, g_X);
    cudaGetSymbolAddress((void**)&pH0, g_H0);
    cudaGetSymbolAddress((void**)&pH1, g_H1);
    cudaGetSymbolAddress((void**)&pF, g_F);
    cudaGetSymbolAddress((void**)&pW0t, g_W0t);
    cudaGetSymbolAddress((void**)&pWfct, g_Wfct);
    cudaGetSymbolAddress((void**)&pWbt, g_Wbt);

    cudaFuncSetAttribute(gemm_mma_kernel<0>, cudaFuncAttributeMaxDynamicSharedMemorySize, G_SMEM);
    cudaFuncSetAttribute(gemm_mma_kernel<1>, cudaFuncAttributeMaxDynamicSharedMemorySize, G_SMEM);
    cudaFuncSetAttribute(gemm_mma_kernel<3>, cudaFuncAttributeMaxDynamicSharedMemorySize, G_SMEM);

    timegate_kernel<<<BNCNT, 128>>>(history, tod, emb, tg1_w, tg1_b, tg2_w, tg2_b, tg3_w, tg3_b);
    dp_kernel<<<(NN * NN + 255) / 256, 256>>>(emb);
    pad_zero_kernel<<<((MPAD - MROWS) * CONCATN + 255) / 256, 256>>>();
    transpose_all_kernel<<<2016, dim3(32, 8)>>>(fc0_w, fc_w, back_w);
    build_hist_kernel<<<BNCNT, 256>>>(emb);

    const int GMX = MPAD / G_BM;   // 140
    for (int i = 0; i < 3; i++) {
        gemm_mma_kernel<0><<<dim3(GMX, 1), 256, G_SMEM>>>(
            pX, pW0t + (size_t)i * HH * CONCATN, fc0_b + i * HH, pH0, pH0, HH, CONCATN);
        gemm_mma_kernel<0><<<dim3(GMX, 1), 256, G_SMEM>>>(
            pH0, pWfct + ((size_t)i * 2 + 0) * HH * HH, fc_b + (i * 2 + 0) * HH, pH1, pH1, HH, HH);
        gemm_mma_kernel<0><<<dim3(GMX, 1), 256, G_SMEM>>>(
            pH1, pWfct + ((size_t)i * 2 + 1) * HH * HH, fc_b + (i * 2 + 1) * HH, pH0, pH0, HH, HH);
        if (i == 0)
            sgemm_kernel<2><<<dim3(MPAD / BM, 1), 256>>>(
                pH0, fore_w + (size_t)i * HH * HORZ, fore_b + i * HORZ, pF, MPAD, HORZ, HH);
        else
            sgemm_kernel<3><<<dim3(MPAD / BM, 1), 256>>>(
                pH0, fore_w + (size_t)i * HH * HORZ, fore_b + i * HORZ, pF, MPAD, HORZ, HH);
        if (i < 2)
            gemm_mma_kernel<1><<<dim3(GMX, CONCATN / G_BN), 256, G_SMEM>>>(
                pH0, pWbt + (size_t)i * CONCATN * HH, back_b + (size_t)i * CONCATN, pX, pX, CONCATN, HH);
        else
            gemm_mma_kernel<3><<<dim3(GMX, CONCATN / G_BN), 256, G_SMEM>>>(
                pH0, pWbt + (size_t)i * CONCATN * HH, back_b + (size_t)i * CONCATN, out, pX, CONCATN, HH);
    }

    forecast_out_kernel<<<(BNCNT * HORZ * CC + 255) / 256, 256>>>(out + (size_t)MROWS * CONCATN);
}